// round 3
// baseline (speedup 1.0000x reference)
#include <cuda_runtime.h>
#include <cuda_bf16.h>
#include <cstdint>

// Problem constants (fixed by the dataset).
#define NN      50000
#define NE      1600000
#define IN_DIM  256
#define OUTF    128          // N_HEADS * OUT_DIM
#define NHEADS  4
#define HD      32           // OUT_DIM per head
#define ALPHA_SLOPE 0.2f

// ---------------- scratch (device globals; no allocation allowed) -----------
__device__ float g_hprime[(size_t)NN * OUTF];     // 25.6 MB
__device__ float g_alpha_src[(size_t)NN * NHEADS];
__device__ float g_alpha_dst[(size_t)NN * NHEADS];
__device__ float g_att[(size_t)NE * NHEADS];      // 25.6 MB
__device__ int   g_m[(size_t)NN * NHEADS];        // encoded float max keys
__device__ float g_s[(size_t)NN * NHEADS];

// ---------------- K1: tiled fp32 GEMM  C[NN,128] = A[NN,256] @ B[256,128] ----
#define BM 128
#define BN 128
#define BK 16
#define TM 8
#define TN 8

__global__ __launch_bounds__(256, 2)
void gemm_kernel(const float* __restrict__ A, const float* __restrict__ B,
                 float* __restrict__ C) {
    __shared__ float As[BK][BM + 4];   // +4 pad: avoids worst store conflicts
    __shared__ float Bs[BK][BN];

    const int tid = threadIdx.x;           // 256 threads
    const int m0  = blockIdx.x * BM;
    const int ty  = tid >> 4;              // 0..15
    const int tx  = tid & 15;              // 0..15

    float acc[TM][TN];
#pragma unroll
    for (int i = 0; i < TM; i++)
#pragma unroll
        for (int j = 0; j < TN; j++) acc[i][j] = 0.f;

    for (int kt = 0; kt < IN_DIM; kt += BK) {
        // Load A tile (128 x 16) transposed into As[k][m]
#pragma unroll
        for (int it = 0; it < 2; it++) {
            int idx = tid + it * 256;      // 0..511
            int row = idx >> 2;            // 0..127
            int c4  = (idx & 3) * 4;       // 0,4,8,12
            float4 v = make_float4(0.f, 0.f, 0.f, 0.f);
            int grow = m0 + row;
            if (grow < NN)
                v = *reinterpret_cast<const float4*>(A + (size_t)grow * IN_DIM + kt + c4);
            As[c4 + 0][row] = v.x;
            As[c4 + 1][row] = v.y;
            As[c4 + 2][row] = v.z;
            As[c4 + 3][row] = v.w;
        }
        // Load B tile (16 x 128) as-is
#pragma unroll
        for (int it = 0; it < 2; it++) {
            int idx = tid + it * 256;
            int row = idx >> 5;            // 0..15
            int col = (idx & 31) * 4;
            *reinterpret_cast<float4*>(&Bs[row][col]) =
                *reinterpret_cast<const float4*>(B + (size_t)(kt + row) * BN + col);
        }
        __syncthreads();

#pragma unroll
        for (int k = 0; k < BK; k++) {
            float ra[TM], rb[TN];
            float4 a0 = *reinterpret_cast<const float4*>(&As[k][ty * TM]);
            float4 a1 = *reinterpret_cast<const float4*>(&As[k][ty * TM + 4]);
            float4 b0 = *reinterpret_cast<const float4*>(&Bs[k][tx * TN]);
            float4 b1 = *reinterpret_cast<const float4*>(&Bs[k][tx * TN + 4]);
            ra[0]=a0.x; ra[1]=a0.y; ra[2]=a0.z; ra[3]=a0.w;
            ra[4]=a1.x; ra[5]=a1.y; ra[6]=a1.z; ra[7]=a1.w;
            rb[0]=b0.x; rb[1]=b0.y; rb[2]=b0.z; rb[3]=b0.w;
            rb[4]=b1.x; rb[5]=b1.y; rb[6]=b1.z; rb[7]=b1.w;
#pragma unroll
            for (int i = 0; i < TM; i++)
#pragma unroll
                for (int j = 0; j < TN; j++)
                    acc[i][j] += ra[i] * rb[j];
        }
        __syncthreads();
    }

#pragma unroll
    for (int i = 0; i < TM; i++) {
        int grow = m0 + ty * TM + i;
        if (grow < NN) {
            float4 v0 = make_float4(acc[i][0], acc[i][1], acc[i][2], acc[i][3]);
            float4 v1 = make_float4(acc[i][4], acc[i][5], acc[i][6], acc[i][7]);
            *reinterpret_cast<float4*>(C + (size_t)grow * BN + tx * TN)     = v0;
            *reinterpret_cast<float4*>(C + (size_t)grow * BN + tx * TN + 4) = v1;
        }
    }
}

// ---------------- K2: per-node attention scalars ----------------------------
// alpha_src[n,h] = sum_d hprime[n,h,d] * a[d,h]
// alpha_dst[n,h] = sum_d hprime[n,h,d] * a[32+d,h]     a is [64,4] row-major
__global__ __launch_bounds__(128)
void alpha_kernel(const float* __restrict__ hp, const float* __restrict__ a,
                  float* __restrict__ asrc, float* __restrict__ adst) {
    int n = blockIdx.x;
    int t = threadIdx.x;                 // 128
    int head = t >> 5;                   // warp index == head
    int d    = t & 31;
    float v  = hp[(size_t)n * OUTF + head * HD + d];
    float s1 = v * a[d * NHEADS + head];
    float s2 = v * a[(HD + d) * NHEADS + head];
#pragma unroll
    for (int o = 16; o > 0; o >>= 1) {
        s1 += __shfl_down_sync(0xffffffffu, s1, o);
        s2 += __shfl_down_sync(0xffffffffu, s2, o);
    }
    if (d == 0) {
        asrc[n * NHEADS + head] = s1;
        adst[n * NHEADS + head] = s2;
    }
}

// ---------------- K3: edge attention logits + segment max -------------------
__device__ __forceinline__ int f2key(float f) {
    int iv = __float_as_int(f);
    return iv >= 0 ? iv : (iv ^ 0x7FFFFFFF);
}
__device__ __forceinline__ float key2f(int k) {
    return k >= 0 ? __int_as_float(k) : __int_as_float(k ^ 0x7FFFFFFF);
}

__global__ __launch_bounds__(256)
void att_kernel(const int* __restrict__ adj,
                const float* __restrict__ asrc, const float* __restrict__ adst,
                float* __restrict__ att, int* __restrict__ mArr) {
    int i = blockIdx.x * blockDim.x + threadIdx.x;
    if (i >= NE * NHEADS) return;
    int e    = i >> 2;
    int head = i & 3;
    int s = adj[e];
    int d = adj[NE + e];
    float v = asrc[s * NHEADS + head] + adst[d * NHEADS + head];
    v = v > 0.f ? v : ALPHA_SLOPE * v;
    att[i] = v;
    atomicMax(&mArr[d * NHEADS + head], f2key(v));
}

// ---------------- K4: exp + segment sum + unnormalized aggregation ----------
// One warp per edge. Lane l handles output floats [4l, 4l+4) (head = l>>3).
__global__ __launch_bounds__(256)
void agg_kernel(const int* __restrict__ adj, const float* __restrict__ att,
                const int* __restrict__ mArr, const float* __restrict__ hp,
                float* __restrict__ sArr, float* __restrict__ out) {
    int wid  = (blockIdx.x * blockDim.x + threadIdx.x) >> 5;
    int lane = threadIdx.x & 31;
    if (wid >= NE) return;
    int src  = adj[wid];
    int dst  = adj[NE + wid];
    int head = lane >> 3;

    float v  = att[(size_t)wid * NHEADS + head];
    float m  = key2f(mArr[dst * NHEADS + head]);
    float ev = __expf(v - m);

    if ((lane & 7) == 0)
        atomicAdd(&sArr[dst * NHEADS + head], ev);   // compiles to RED

    float4 hv = *reinterpret_cast<const float4*>(hp + (size_t)src * OUTF + lane * 4);
    float wx = ev * hv.x, wy = ev * hv.y, wz = ev * hv.z, ww = ev * hv.w;
    float* dsto = out + (size_t)dst * OUTF + lane * 4;
    asm volatile("red.global.add.v4.f32 [%0], {%1, %2, %3, %4};"
                 :: "l"(dsto), "f"(wx), "f"(wy), "f"(wz), "f"(ww) : "memory");
}

// ---------------- K5: normalize by segment sum ------------------------------
__global__ __launch_bounds__(256)
void norm_kernel(const float* __restrict__ sArr, float* __restrict__ out) {
    int i = blockIdx.x * blockDim.x + threadIdx.x;
    if (i >= NN * OUTF) return;
    int n    = i >> 7;
    int head = (i >> 5) & 3;
    float sv = sArr[n * NHEADS + head];
    out[i] = (sv > 0.f) ? out[i] / sv : 0.f;
}

// ---------------- launch ----------------------------------------------------
extern "C" void kernel_launch(void* const* d_in, const int* in_sizes, int n_in,
                              void* d_out, int out_size) {
    const float* h   = (const float*)d_in[0];   // [50000, 256]
    const int*   adj = (const int*)  d_in[1];   // [2, 1600000]
    const float* W   = (const float*)d_in[2];   // [256, 128]
    const float* a   = (const float*)d_in[3];   // [64, 4]
    float*       out = (float*)d_out;           // [50000, 128]

    void *p_hp, *p_as, *p_ad, *p_att, *p_m, *p_s;
    cudaGetSymbolAddress(&p_hp,  g_hprime);
    cudaGetSymbolAddress(&p_as,  g_alpha_src);
    cudaGetSymbolAddress(&p_ad,  g_alpha_dst);
    cudaGetSymbolAddress(&p_att, g_att);
    cudaGetSymbolAddress(&p_m,   g_m);
    cudaGetSymbolAddress(&p_s,   g_s);

    // Init: out=0, s=0, m = byte 0x80 pattern (decodes to -3.39e38, a valid
    // "-inf" sentinel for attention logits).
    cudaMemsetAsync(d_out, 0,    (size_t)NN * OUTF * sizeof(float));
    cudaMemsetAsync(p_s,   0,    (size_t)NN * NHEADS * sizeof(float));
    cudaMemsetAsync(p_m,   0x80, (size_t)NN * NHEADS * sizeof(int));

    // 1) h_prime = h @ W
    gemm_kernel<<<(NN + BM - 1) / BM, 256>>>(h, W, (float*)p_hp);

    // 2) per-node attention scalars
    alpha_kernel<<<NN, 128>>>((const float*)p_hp, a, (float*)p_as, (float*)p_ad);

    // 3) edge logits + segment max
    att_kernel<<<(NE * NHEADS + 255) / 256, 256>>>(adj, (const float*)p_as,
                                                   (const float*)p_ad,
                                                   (float*)p_att, (int*)p_m);

    // 4) exp + segment sum + unnormalized scatter-aggregate (warp per edge)
    agg_kernel<<<(NE * 32 + 255) / 256, 256>>>(adj, (const float*)p_att,
                                               (const int*)p_m,
                                               (const float*)p_hp,
                                               (float*)p_s, out);

    // 5) normalize
    norm_kernel<<<(NN * OUTF + 255) / 256, 256>>>((const float*)p_s, out);
}

// round 4
// speedup vs baseline: 1.2862x; 1.2862x over previous
#include <cuda_runtime.h>
#include <cuda_bf16.h>
#include <cstdint>

// Problem constants (fixed by the dataset).
#define NN      50000
#define NE      1600000
#define IN_DIM  256
#define OUTF    128          // N_HEADS * OUT_DIM
#define NHEADS  4
#define HD      32           // OUT_DIM per head
#define ALPHA_SLOPE 0.2f

// ---------------- scratch (device globals; no allocation allowed) -----------
__device__ float g_hprime[(size_t)NN * OUTF];     // 25.6 MB
__device__ float g_alpha_src[(size_t)NN * NHEADS];
__device__ float g_alpha_dst[(size_t)NN * NHEADS];
__device__ int   g_deg[NN];
__device__ int   g_row[NN];
__device__ int   g_cursor[NN];
__device__ int   g_src_sorted[NE];                // 6.4 MB

// ---------------- K1: fp32x2 GEMM  C[NN,128] = A[NN,256] @ B[256,128] -------
#define BM 128
#define BN 128
#define BK 16
#define TM 8
#define TN 8

#define FMA_F32X2(d, a, b, c) \
    asm("fma.rn.f32x2 %0, %1, %2, %3;" : "=l"(d) : "l"(a), "l"(b), "l"(c))

__global__ __launch_bounds__(256, 2)
void gemm_kernel(const float* __restrict__ A, const float* __restrict__ B,
                 float* __restrict__ C) {
    __shared__ float As[BK][BM + 4];
    __shared__ float Bs[BK][BN];

    const int tid = threadIdx.x;           // 256 threads
    const int m0  = blockIdx.x * BM;
    const int ty  = tid >> 4;              // 0..15
    const int tx  = tid & 15;              // 0..15

    // acc pairs along columns: accp[i][j2] holds cols (2*j2, 2*j2+1) of row i
    unsigned long long accp[TM][TN / 2];
#pragma unroll
    for (int i = 0; i < TM; i++)
#pragma unroll
        for (int j = 0; j < TN / 2; j++) accp[i][j] = 0ull;

    for (int kt = 0; kt < IN_DIM; kt += BK) {
        // Load A tile (128 x 16) transposed into As[k][m]
#pragma unroll
        for (int it = 0; it < 2; it++) {
            int idx = tid + it * 256;      // 0..511
            int row = idx >> 2;            // 0..127
            int c4  = (idx & 3) * 4;       // 0,4,8,12
            float4 v = make_float4(0.f, 0.f, 0.f, 0.f);
            int grow = m0 + row;
            if (grow < NN)
                v = *reinterpret_cast<const float4*>(A + (size_t)grow * IN_DIM + kt + c4);
            As[c4 + 0][row] = v.x;
            As[c4 + 1][row] = v.y;
            As[c4 + 2][row] = v.z;
            As[c4 + 3][row] = v.w;
        }
        // Load B tile (16 x 128)
#pragma unroll
        for (int it = 0; it < 2; it++) {
            int idx = tid + it * 256;
            int row = idx >> 5;            // 0..15
            int col = (idx & 31) * 4;
            *reinterpret_cast<float4*>(&Bs[row][col]) =
                *reinterpret_cast<const float4*>(B + (size_t)(kt + row) * BN + col);
        }
        __syncthreads();

#pragma unroll
        for (int k = 0; k < BK; k++) {
            float4 a0 = *reinterpret_cast<const float4*>(&As[k][ty * TM]);
            float4 a1 = *reinterpret_cast<const float4*>(&As[k][ty * TM + 4]);
            // B column pairs as packed f32x2 (8B aligned: tx*TN is a multiple of 8)
            ulonglong2 b01 = *reinterpret_cast<const ulonglong2*>(&Bs[k][tx * TN]);
            ulonglong2 b23 = *reinterpret_cast<const ulonglong2*>(&Bs[k][tx * TN + 4]);
            float ra[TM] = {a0.x, a0.y, a0.z, a0.w, a1.x, a1.y, a1.z, a1.w};
#pragma unroll
            for (int i = 0; i < TM; i++) {
                unsigned long long a2;
                unsigned int rbits = __float_as_uint(ra[i]);
                asm("mov.b64 %0, {%1, %1};" : "=l"(a2) : "r"(rbits));
                FMA_F32X2(accp[i][0], a2, b01.x, accp[i][0]);
                FMA_F32X2(accp[i][1], a2, b01.y, accp[i][1]);
                FMA_F32X2(accp[i][2], a2, b23.x, accp[i][2]);
                FMA_F32X2(accp[i][3], a2, b23.y, accp[i][3]);
            }
        }
        __syncthreads();
    }

#pragma unroll
    for (int i = 0; i < TM; i++) {
        int grow = m0 + ty * TM + i;
        if (grow < NN) {
            // accp[i][] is 8 floats in column order (little-endian lo = even col)
            const float* f = reinterpret_cast<const float*>(accp[i]);
            float4 v0 = make_float4(f[0], f[1], f[2], f[3]);
            float4 v1 = make_float4(f[4], f[5], f[6], f[7]);
            *reinterpret_cast<float4*>(C + (size_t)grow * BN + tx * TN)     = v0;
            *reinterpret_cast<float4*>(C + (size_t)grow * BN + tx * TN + 4) = v1;
        }
    }
}

// ---------------- K2: per-node attention scalars ----------------------------
__global__ __launch_bounds__(128)
void alpha_kernel(const float* __restrict__ hp, const float* __restrict__ a,
                  float* __restrict__ asrc, float* __restrict__ adst) {
    int n = blockIdx.x;
    int t = threadIdx.x;                 // 128
    int head = t >> 5;
    int d    = t & 31;
    float v  = hp[(size_t)n * OUTF + head * HD + d];
    float s1 = v * a[d * NHEADS + head];
    float s2 = v * a[(HD + d) * NHEADS + head];
#pragma unroll
    for (int o = 16; o > 0; o >>= 1) {
        s1 += __shfl_down_sync(0xffffffffu, s1, o);
        s2 += __shfl_down_sync(0xffffffffu, s2, o);
    }
    if (d == 0) {
        asrc[n * NHEADS + head] = s1;
        adst[n * NHEADS + head] = s2;
    }
}

// ---------------- K3: degree histogram --------------------------------------
__global__ __launch_bounds__(256)
void hist_kernel(const int* __restrict__ adj, int* __restrict__ deg) {
    int i = blockIdx.x * blockDim.x + threadIdx.x;
    if (i >= NE) return;
    atomicAdd(&deg[adj[NE + i]], 1);
}

// ---------------- K4: exclusive scan over 50k degrees (single block) --------
#define SCAN_T 1024
__global__ __launch_bounds__(SCAN_T)
void scan_kernel(const int* __restrict__ deg, int* __restrict__ row,
                 int* __restrict__ cursor) {
    const int ITEMS = (NN + SCAN_T - 1) / SCAN_T;    // 49
    int tid  = threadIdx.x;
    int base = tid * ITEMS;
    int s = 0;
#pragma unroll 4
    for (int k = 0; k < ITEMS; k++) {
        int i = base + k;
        if (i < NN) s += deg[i];
    }
    // block exclusive scan of per-thread sums
    __shared__ int warp_sums[32];
    int lane = tid & 31, wid = tid >> 5;
    int x = s;
#pragma unroll
    for (int o = 1; o < 32; o <<= 1) {
        int y = __shfl_up_sync(0xffffffffu, x, o);
        if (lane >= o) x += y;
    }
    if (lane == 31) warp_sums[wid] = x;
    __syncthreads();
    if (wid == 0) {
        int w = warp_sums[lane];
#pragma unroll
        for (int o = 1; o < 32; o <<= 1) {
            int y = __shfl_up_sync(0xffffffffu, w, o);
            if (lane >= o) w += y;
        }
        warp_sums[lane] = w;
    }
    __syncthreads();
    int excl = x - s + (wid > 0 ? warp_sums[wid - 1] : 0);
    int p = excl;
    for (int k = 0; k < ITEMS; k++) {
        int i = base + k;
        if (i < NN) {
            row[i]    = p;
            cursor[i] = p;
            p += deg[i];
        }
    }
}

// ---------------- K5: scatter src indices into CSR order --------------------
__global__ __launch_bounds__(256)
void scatter_kernel(const int* __restrict__ adj, int* __restrict__ cursor,
                    int* __restrict__ srcs) {
    int i = blockIdx.x * blockDim.x + threadIdx.x;
    if (i >= NE) return;
    int s = adj[i];
    int d = adj[NE + i];
    int pos = atomicAdd(&cursor[d], 1);
    srcs[pos] = s;
}

// ---------------- K6: warp-per-node softmax + aggregation (no atomics) ------
// Lane l owns output floats [4l, 4l+4); head = l>>3.
__global__ __launch_bounds__(256)
void agg_kernel(const int* __restrict__ row, const int* __restrict__ deg,
                const int* __restrict__ srcs,
                const float* __restrict__ asrc, const float* __restrict__ adst,
                const float* __restrict__ hp, float* __restrict__ out) {
    int n = (blockIdx.x * blockDim.x + threadIdx.x) >> 5;
    if (n >= NN) return;
    int lane = threadIdx.x & 31;
    int head = lane >> 3;

    int beg = row[n];
    int dn  = deg[n];
    float au = __ldg(&adst[n * NHEADS + head]);

    float accx = 0.f, accy = 0.f, accz = 0.f, accw = 0.f;
    float ssum = 0.f;

    if (dn > 0) {
        int sc = __ldg(&srcs[beg]);                      // prefetched src
        for (int j = 0; j < dn; ++j) {
            int scn = (j + 1 < dn) ? __ldg(&srcs[beg + j + 1]) : 0;
            float v = __ldg(&asrc[sc * NHEADS + head]) + au;
            v = v > 0.f ? v : ALPHA_SLOPE * v;
            float ev = __expf(v);                        // no max-shift needed (|v| <~ 20)
            const float4 hv = *reinterpret_cast<const float4*>(
                hp + (size_t)sc * OUTF + lane * 4);
            ssum += ev;
            accx += ev * hv.x;
            accy += ev * hv.y;
            accz += ev * hv.z;
            accw += ev * hv.w;
            sc = scn;
        }
        float inv = 1.0f / ssum;                         // all lanes in head group agree
        accx *= inv; accy *= inv; accz *= inv; accw *= inv;
    }
    *reinterpret_cast<float4*>(out + (size_t)n * OUTF + lane * 4) =
        make_float4(accx, accy, accz, accw);
}

// ---------------- launch ----------------------------------------------------
extern "C" void kernel_launch(void* const* d_in, const int* in_sizes, int n_in,
                              void* d_out, int out_size) {
    const float* h   = (const float*)d_in[0];   // [50000, 256]
    const int*   adj = (const int*)  d_in[1];   // [2, 1600000]
    const float* W   = (const float*)d_in[2];   // [256, 128]
    const float* a   = (const float*)d_in[3];   // [64, 4]
    float*       out = (float*)d_out;           // [50000, 128]

    void *p_hp, *p_as, *p_ad, *p_deg, *p_row, *p_cur, *p_srcs;
    cudaGetSymbolAddress(&p_hp,   g_hprime);
    cudaGetSymbolAddress(&p_as,   g_alpha_src);
    cudaGetSymbolAddress(&p_ad,   g_alpha_dst);
    cudaGetSymbolAddress(&p_deg,  g_deg);
    cudaGetSymbolAddress(&p_row,  g_row);
    cudaGetSymbolAddress(&p_cur,  g_cursor);
    cudaGetSymbolAddress(&p_srcs, g_src_sorted);

    cudaMemsetAsync(p_deg, 0, NN * sizeof(int));

    // 1) h_prime = h @ W   (fp32x2 packed FMA)
    gemm_kernel<<<(NN + BM - 1) / BM, 256>>>(h, W, (float*)p_hp);

    // 2) per-node attention scalars
    alpha_kernel<<<NN, 128>>>((const float*)p_hp, a, (float*)p_as, (float*)p_ad);

    // 3) CSR build: histogram -> scan -> scatter
    hist_kernel<<<(NE + 255) / 256, 256>>>(adj, (int*)p_deg);
    scan_kernel<<<1, SCAN_T>>>((const int*)p_deg, (int*)p_row, (int*)p_cur);
    scatter_kernel<<<(NE + 255) / 256, 256>>>(adj, (int*)p_cur, (int*)p_srcs);

    // 4) warp-per-node gather softmax-aggregate (atomic-free, fused normalize)
    agg_kernel<<<(NN * 32 + 255) / 256, 256>>>(
        (const int*)p_row, (const int*)p_deg, (const int*)p_srcs,
        (const float*)p_as, (const float*)p_ad, (const float*)p_hp, out);
}

// round 5
// speedup vs baseline: 1.6757x; 1.3029x over previous
#include <cuda_runtime.h>
#include <cuda_bf16.h>
#include <cstdint>

// Problem constants (fixed by the dataset).
#define NN      50000
#define NE      1600000
#define IN_DIM  256
#define OUTF    128          // N_HEADS * OUT_DIM
#define NHEADS  4
#define HD      32           // OUT_DIM per head
#define ALPHA_SLOPE 0.2f

#define NB      ((NN + 255) / 256)    // 196 scan blocks

// ---------------- scratch (device globals; no allocation allowed) -----------
__device__ float g_hprime[(size_t)NN * OUTF];     // 25.6 MB
__device__ float g_alpha_src[(size_t)NN * NHEADS];
__device__ float g_alpha_dst[(size_t)NN * NHEADS];
__device__ int   g_deg[NN];
__device__ int   g_row[NN];
__device__ int   g_cursor[NN];
__device__ int   g_src_sorted[NE];                // 6.4 MB
__device__ int   g_bsum[NB];
__device__ int   g_boff[NB];

// ---------------- K1: fp32x2 GEMM  C[NN,128] = A[NN,256] @ B[256,128] -------
#define BM 128
#define BN 128
#define BK 16
#define TM 8
#define TN 8

#define FMA_F32X2(d, a, b, c) \
    asm("fma.rn.f32x2 %0, %1, %2, %3;" : "=l"(d) : "l"(a), "l"(b), "l"(c))

__global__ __launch_bounds__(256, 2)
void gemm_kernel(const float* __restrict__ A, const float* __restrict__ B,
                 float* __restrict__ C) {
    __shared__ float As[BK][BM + 4];
    __shared__ float Bs[BK][BN];

    const int tid = threadIdx.x;           // 256 threads
    const int m0  = blockIdx.x * BM;
    const int ty  = tid >> 4;              // 0..15
    const int tx  = tid & 15;              // 0..15

    unsigned long long accp[TM][TN / 2];
#pragma unroll
    for (int i = 0; i < TM; i++)
#pragma unroll
        for (int j = 0; j < TN / 2; j++) accp[i][j] = 0ull;

    for (int kt = 0; kt < IN_DIM; kt += BK) {
#pragma unroll
        for (int it = 0; it < 2; it++) {
            int idx = tid + it * 256;      // 0..511
            int row = idx >> 2;            // 0..127
            int c4  = (idx & 3) * 4;       // 0,4,8,12
            float4 v = make_float4(0.f, 0.f, 0.f, 0.f);
            int grow = m0 + row;
            if (grow < NN)
                v = *reinterpret_cast<const float4*>(A + (size_t)grow * IN_DIM + kt + c4);
            As[c4 + 0][row] = v.x;
            As[c4 + 1][row] = v.y;
            As[c4 + 2][row] = v.z;
            As[c4 + 3][row] = v.w;
        }
#pragma unroll
        for (int it = 0; it < 2; it++) {
            int idx = tid + it * 256;
            int row = idx >> 5;            // 0..15
            int col = (idx & 31) * 4;
            *reinterpret_cast<float4*>(&Bs[row][col]) =
                *reinterpret_cast<const float4*>(B + (size_t)(kt + row) * BN + col);
        }
        __syncthreads();

#pragma unroll
        for (int k = 0; k < BK; k++) {
            float4 a0 = *reinterpret_cast<const float4*>(&As[k][ty * TM]);
            float4 a1 = *reinterpret_cast<const float4*>(&As[k][ty * TM + 4]);
            ulonglong2 b01 = *reinterpret_cast<const ulonglong2*>(&Bs[k][tx * TN]);
            ulonglong2 b23 = *reinterpret_cast<const ulonglong2*>(&Bs[k][tx * TN + 4]);
            float ra[TM] = {a0.x, a0.y, a0.z, a0.w, a1.x, a1.y, a1.z, a1.w};
#pragma unroll
            for (int i = 0; i < TM; i++) {
                unsigned long long a2;
                unsigned int rbits = __float_as_uint(ra[i]);
                asm("mov.b64 %0, {%1, %1};" : "=l"(a2) : "r"(rbits));
                FMA_F32X2(accp[i][0], a2, b01.x, accp[i][0]);
                FMA_F32X2(accp[i][1], a2, b01.y, accp[i][1]);
                FMA_F32X2(accp[i][2], a2, b23.x, accp[i][2]);
                FMA_F32X2(accp[i][3], a2, b23.y, accp[i][3]);
            }
        }
        __syncthreads();
    }

#pragma unroll
    for (int i = 0; i < TM; i++) {
        int grow = m0 + ty * TM + i;
        if (grow < NN) {
            const float* f = reinterpret_cast<const float*>(accp[i]);
            float4 v0 = make_float4(f[0], f[1], f[2], f[3]);
            float4 v1 = make_float4(f[4], f[5], f[6], f[7]);
            *reinterpret_cast<float4*>(C + (size_t)grow * BN + tx * TN)     = v0;
            *reinterpret_cast<float4*>(C + (size_t)grow * BN + tx * TN + 4) = v1;
        }
    }
}

// ---------------- K2: per-node attention scalars ----------------------------
__global__ __launch_bounds__(128)
void alpha_kernel(const float* __restrict__ hp, const float* __restrict__ a,
                  float* __restrict__ asrc, float* __restrict__ adst) {
    int n = blockIdx.x;
    int t = threadIdx.x;                 // 128
    int head = t >> 5;
    int d    = t & 31;
    float v  = hp[(size_t)n * OUTF + head * HD + d];
    float s1 = v * a[d * NHEADS + head];
    float s2 = v * a[(HD + d) * NHEADS + head];
#pragma unroll
    for (int o = 16; o > 0; o >>= 1) {
        s1 += __shfl_down_sync(0xffffffffu, s1, o);
        s2 += __shfl_down_sync(0xffffffffu, s2, o);
    }
    if (d == 0) {
        asrc[n * NHEADS + head] = s1;
        adst[n * NHEADS + head] = s2;
    }
}

// ---------------- K3: degree histogram --------------------------------------
__global__ __launch_bounds__(256)
void hist_kernel(const int* __restrict__ adj, int* __restrict__ deg) {
    int i = blockIdx.x * blockDim.x + threadIdx.x;
    if (i >= NE) return;
    atomicAdd(&deg[adj[NE + i]], 1);
}

// ---------------- K4: multi-block exclusive scan of degrees -----------------
// Phase a: per-block sums of 256 degrees each.
__global__ __launch_bounds__(256)
void bsum_kernel(const int* __restrict__ deg, int* __restrict__ bsum) {
    int i = blockIdx.x * 256 + threadIdx.x;
    int v = (i < NN) ? deg[i] : 0;
    int lane = threadIdx.x & 31, wid = threadIdx.x >> 5;
#pragma unroll
    for (int o = 16; o > 0; o >>= 1) v += __shfl_down_sync(0xffffffffu, v, o);
    __shared__ int ws[8];
    if (lane == 0) ws[wid] = v;
    __syncthreads();
    if (threadIdx.x == 0) {
        int s = 0;
#pragma unroll
        for (int w = 0; w < 8; w++) s += ws[w];
        bsum[blockIdx.x] = s;
    }
}

// Phase b: exclusive scan of NB (=196) block sums, single block.
__global__ __launch_bounds__(256)
void bscan_kernel(const int* __restrict__ bsum, int* __restrict__ boff) {
    int tid = threadIdx.x;
    int v = (tid < NB) ? bsum[tid] : 0;
    int lane = tid & 31, wid = tid >> 5;
    int x = v;
#pragma unroll
    for (int o = 1; o < 32; o <<= 1) {
        int y = __shfl_up_sync(0xffffffffu, x, o);
        if (lane >= o) x += y;
    }
    __shared__ int ws[8];
    if (lane == 31) ws[wid] = x;
    __syncthreads();
    if (wid == 0 && lane < 8) {
        int w = ws[lane];
#pragma unroll
        for (int o = 1; o < 8; o <<= 1) {
            int y = __shfl_up_sync(0x000000ffu, w, o);
            if (lane >= o) w += y;
        }
        ws[lane] = w;
    }
    __syncthreads();
    int incl = x + (wid > 0 ? ws[wid - 1] : 0);
    if (tid < NB) boff[tid] = incl - v;      // exclusive
}

// Phase c: per-block exclusive scan + block offset -> row, cursor.
__global__ __launch_bounds__(256)
void scanf_kernel(const int* __restrict__ deg, const int* __restrict__ boff,
                  int* __restrict__ row, int* __restrict__ cursor) {
    int i = blockIdx.x * 256 + threadIdx.x;
    int v = (i < NN) ? deg[i] : 0;
    int lane = threadIdx.x & 31, wid = threadIdx.x >> 5;
    int x = v;
#pragma unroll
    for (int o = 1; o < 32; o <<= 1) {
        int y = __shfl_up_sync(0xffffffffu, x, o);
        if (lane >= o) x += y;
    }
    __shared__ int ws[8];
    if (lane == 31) ws[wid] = x;
    __syncthreads();
    if (wid == 0 && lane < 8) {
        int w = ws[lane];
#pragma unroll
        for (int o = 1; o < 8; o <<= 1) {
            int y = __shfl_up_sync(0x000000ffu, w, o);
            if (lane >= o) w += y;
        }
        ws[lane] = w;
    }
    __syncthreads();
    int excl = x - v + (wid > 0 ? ws[wid - 1] : 0) + boff[blockIdx.x];
    if (i < NN) {
        row[i]    = excl;
        cursor[i] = excl;
    }
}

// ---------------- K5: scatter src indices into CSR order --------------------
__global__ __launch_bounds__(256)
void scatter_kernel(const int* __restrict__ adj, int* __restrict__ cursor,
                    int* __restrict__ srcs) {
    int i = blockIdx.x * blockDim.x + threadIdx.x;
    if (i >= NE) return;
    int s = adj[i];
    int d = adj[NE + i];
    int pos = atomicAdd(&cursor[d], 1);
    srcs[pos] = s;
}

// ---------------- K6: warp-per-node softmax + aggregation (no atomics) ------
// Lane l owns output floats [4l, 4l+4); head = l>>3.
__global__ __launch_bounds__(256)
void agg_kernel(const int* __restrict__ row, const int* __restrict__ deg,
                const int* __restrict__ srcs,
                const float* __restrict__ asrc, const float* __restrict__ adst,
                const float* __restrict__ hp, float* __restrict__ out) {
    int n = (blockIdx.x * blockDim.x + threadIdx.x) >> 5;
    if (n >= NN) return;
    int lane = threadIdx.x & 31;
    int head = lane >> 3;

    int beg = row[n];
    int dn  = deg[n];
    float au = __ldg(&adst[n * NHEADS + head]);

    float accx = 0.f, accy = 0.f, accz = 0.f, accw = 0.f;
    float ssum = 0.f;

    if (dn > 0) {
        int sc = __ldg(&srcs[beg]);
        for (int j = 0; j < dn; ++j) {
            int scn = (j + 1 < dn) ? __ldg(&srcs[beg + j + 1]) : 0;
            float v = __ldg(&asrc[sc * NHEADS + head]) + au;
            v = v > 0.f ? v : ALPHA_SLOPE * v;
            float ev = __expf(v);                 // softmax is shift-invariant; |v| small
            const float4 hv = *reinterpret_cast<const float4*>(
                hp + (size_t)sc * OUTF + lane * 4);
            ssum += ev;
            accx += ev * hv.x;
            accy += ev * hv.y;
            accz += ev * hv.z;
            accw += ev * hv.w;
            sc = scn;
        }
        float inv = 1.0f / ssum;
        accx *= inv; accy *= inv; accz *= inv; accw *= inv;
    }
    *reinterpret_cast<float4*>(out + (size_t)n * OUTF + lane * 4) =
        make_float4(accx, accy, accz, accw);
}

// ---------------- launch ----------------------------------------------------
extern "C" void kernel_launch(void* const* d_in, const int* in_sizes, int n_in,
                              void* d_out, int out_size) {
    const float* h   = (const float*)d_in[0];   // [50000, 256]
    const int*   adj = (const int*)  d_in[1];   // [2, 1600000]
    const float* W   = (const float*)d_in[2];   // [256, 128]
    const float* a   = (const float*)d_in[3];   // [64, 4]
    float*       out = (float*)d_out;           // [50000, 128]

    void *p_hp, *p_as, *p_ad, *p_deg, *p_row, *p_cur, *p_srcs, *p_bsum, *p_boff;
    cudaGetSymbolAddress(&p_hp,   g_hprime);
    cudaGetSymbolAddress(&p_as,   g_alpha_src);
    cudaGetSymbolAddress(&p_ad,   g_alpha_dst);
    cudaGetSymbolAddress(&p_deg,  g_deg);
    cudaGetSymbolAddress(&p_row,  g_row);
    cudaGetSymbolAddress(&p_cur,  g_cursor);
    cudaGetSymbolAddress(&p_srcs, g_src_sorted);
    cudaGetSymbolAddress(&p_bsum, g_bsum);
    cudaGetSymbolAddress(&p_boff, g_boff);

    cudaMemsetAsync(p_deg, 0, NN * sizeof(int));

    // 1) h_prime = h @ W   (fp32x2 packed FMA)
    gemm_kernel<<<(NN + BM - 1) / BM, 256>>>(h, W, (float*)p_hp);

    // 2) per-node attention scalars
    alpha_kernel<<<NN, 128>>>((const float*)p_hp, a, (float*)p_as, (float*)p_ad);

    // 3) CSR build: histogram -> multi-block scan -> scatter
    hist_kernel<<<(NE + 255) / 256, 256>>>(adj, (int*)p_deg);
    bsum_kernel<<<NB, 256>>>((const int*)p_deg, (int*)p_bsum);
    bscan_kernel<<<1, 256>>>((const int*)p_bsum, (int*)p_boff);
    scanf_kernel<<<NB, 256>>>((const int*)p_deg, (const int*)p_boff,
                              (int*)p_row, (int*)p_cur);
    scatter_kernel<<<(NE + 255) / 256, 256>>>(adj, (int*)p_cur, (int*)p_srcs);

    // 4) warp-per-node gather softmax-aggregate (atomic-free, fused normalize)
    agg_kernel<<<(NN * 32 + 255) / 256, 256>>>(
        (const int*)p_row, (const int*)p_deg, (const int*)p_srcs,
        (const float*)p_as, (const float*)p_ad, (const float*)p_hp, out);
}

// round 8
// speedup vs baseline: 2.0282x; 1.2104x over previous
#include <cuda_runtime.h>
#include <cuda_bf16.h>
#include <cstdint>

// Problem constants (fixed by the dataset).
#define NN      50000
#define NE      1600000
#define IN_DIM  256
#define OUTF    128          // N_HEADS * OUT_DIM
#define NHEADS  4
#define HD      32           // OUT_DIM per head
#define ALPHA_SLOPE 0.2f

#define NB      ((NN + 255) / 256)    // 196 scan blocks

// ---------------- scratch (device globals; no allocation allowed) -----------
__device__ float g_hprime[(size_t)NN * OUTF];     // 25.6 MB
__device__ float g_alpha_src[(size_t)NN * NHEADS];
__device__ float g_alpha_dst[(size_t)NN * NHEADS];
__device__ int   g_deg[NN];
__device__ int   g_row[NN];
__device__ int   g_cursor[NN];
__device__ int   g_src_sorted[NE];                // 6.4 MB
__device__ int   g_bsum[NB];
__device__ int   g_boff[NB];

// ---------------- K1: fp32x2 GEMM + fused alpha epilogue --------------------
// C[NN,128] = A[NN,256] @ B[256,128]; also emits
//   asrc[n,h] = sum_d C[n,h*32+d] * a[d*4+h]
//   adst[n,h] = sum_d C[n,h*32+d] * a[(32+d)*4+h]
#define BM 128
#define BN 128
#define BK 16
#define TM 8
#define TN 8

#define FMA_F32X2(d, a, b, c) \
    asm("fma.rn.f32x2 %0, %1, %2, %3;" : "=l"(d) : "l"(a), "l"(b), "l"(c))

__global__ __launch_bounds__(256, 2)
void gemm_kernel(const float* __restrict__ A, const float* __restrict__ B,
                 const float* __restrict__ av, float* __restrict__ C,
                 float* __restrict__ asrc, float* __restrict__ adst) {
    __shared__ float As[BK][BM + 4];
    __shared__ float Bs[BK][BN];

    const int tid = threadIdx.x;           // 256 threads
    const int m0  = blockIdx.x * BM;
    const int ty  = tid >> 4;              // 0..15
    const int tx  = tid & 15;              // 0..15

    unsigned long long accp[TM][TN / 2];
#pragma unroll
    for (int i = 0; i < TM; i++)
#pragma unroll
        for (int j = 0; j < TN / 2; j++) accp[i][j] = 0ull;

    for (int kt = 0; kt < IN_DIM; kt += BK) {
#pragma unroll
        for (int it = 0; it < 2; it++) {
            int idx = tid + it * 256;      // 0..511
            int row = idx >> 2;            // 0..127
            int c4  = (idx & 3) * 4;       // 0,4,8,12
            float4 v = make_float4(0.f, 0.f, 0.f, 0.f);
            int grow = m0 + row;
            if (grow < NN)
                v = *reinterpret_cast<const float4*>(A + (size_t)grow * IN_DIM + kt + c4);
            As[c4 + 0][row] = v.x;
            As[c4 + 1][row] = v.y;
            As[c4 + 2][row] = v.z;
            As[c4 + 3][row] = v.w;
        }
#pragma unroll
        for (int it = 0; it < 2; it++) {
            int idx = tid + it * 256;
            int row = idx >> 5;            // 0..15
            int col = (idx & 31) * 4;
            *reinterpret_cast<float4*>(&Bs[row][col]) =
                *reinterpret_cast<const float4*>(B + (size_t)(kt + row) * BN + col);
        }
        __syncthreads();

#pragma unroll
        for (int k = 0; k < BK; k++) {
            float4 a0 = *reinterpret_cast<const float4*>(&As[k][ty * TM]);
            float4 a1 = *reinterpret_cast<const float4*>(&As[k][ty * TM + 4]);
            ulonglong2 b01 = *reinterpret_cast<const ulonglong2*>(&Bs[k][tx * TN]);
            ulonglong2 b23 = *reinterpret_cast<const ulonglong2*>(&Bs[k][tx * TN + 4]);
            float ra[TM] = {a0.x, a0.y, a0.z, a0.w, a1.x, a1.y, a1.z, a1.w};
#pragma unroll
            for (int i = 0; i < TM; i++) {
                unsigned long long a2;
                unsigned int rbits = __float_as_uint(ra[i]);
                asm("mov.b64 %0, {%1, %1};" : "=l"(a2) : "r"(rbits));
                FMA_F32X2(accp[i][0], a2, b01.x, accp[i][0]);
                FMA_F32X2(accp[i][1], a2, b01.y, accp[i][1]);
                FMA_F32X2(accp[i][2], a2, b23.x, accp[i][2]);
                FMA_F32X2(accp[i][3], a2, b23.y, accp[i][3]);
            }
        }
        __syncthreads();
    }

    // ---- epilogue: store C tile + fused alpha dot products ------------------
    // This thread's 8 columns (tx*8 .. tx*8+7) all lie in head h = tx>>2;
    // d-range within head = (tx&3)*8 .. +7.
    const int h      = tx >> 2;
    const int d_base = (tx & 3) * 8;
    float avs[TN], avd[TN];
#pragma unroll
    for (int j = 0; j < TN; j++) {
        avs[j] = __ldg(&av[(d_base + j) * NHEADS + h]);
        avd[j] = __ldg(&av[(32 + d_base + j) * NHEADS + h]);
    }

#pragma unroll
    for (int i = 0; i < TM; i++) {
        int grow = m0 + ty * TM + i;
        const float* f = reinterpret_cast<const float*>(accp[i]);
        if (grow < NN) {
            float4 v0 = make_float4(f[0], f[1], f[2], f[3]);
            float4 v1 = make_float4(f[4], f[5], f[6], f[7]);
            *reinterpret_cast<float4*>(C + (size_t)grow * BN + tx * TN)     = v0;
            *reinterpret_cast<float4*>(C + (size_t)grow * BN + tx * TN + 4) = v1;
        }
        float s = 0.f, t = 0.f;
#pragma unroll
        for (int j = 0; j < TN; j++) {
            s += f[j] * avs[j];
            t += f[j] * avd[j];
        }
        // Reduce across the 4 lanes sharing (row, head): lane bits 0,1 (= tx&3).
        s += __shfl_xor_sync(0xffffffffu, s, 1);
        s += __shfl_xor_sync(0xffffffffu, s, 2);
        t += __shfl_xor_sync(0xffffffffu, t, 1);
        t += __shfl_xor_sync(0xffffffffu, t, 2);
        if (grow < NN && (tx & 3) == 0) {
            asrc[(size_t)grow * NHEADS + h] = s;
            adst[(size_t)grow * NHEADS + h] = t;
        }
    }
}

// ---------------- K3: degree histogram --------------------------------------
__global__ __launch_bounds__(256)
void hist_kernel(const int* __restrict__ adj, int* __restrict__ deg) {
    int i = blockIdx.x * blockDim.x + threadIdx.x;
    if (i >= NE) return;
    atomicAdd(&deg[adj[NE + i]], 1);
}

// ---------------- K4: multi-block exclusive scan of degrees -----------------
__global__ __launch_bounds__(256)
void bsum_kernel(const int* __restrict__ deg, int* __restrict__ bsum) {
    int i = blockIdx.x * 256 + threadIdx.x;
    int v = (i < NN) ? deg[i] : 0;
    int lane = threadIdx.x & 31, wid = threadIdx.x >> 5;
#pragma unroll
    for (int o = 16; o > 0; o >>= 1) v += __shfl_down_sync(0xffffffffu, v, o);
    __shared__ int ws[8];
    if (lane == 0) ws[wid] = v;
    __syncthreads();
    if (threadIdx.x == 0) {
        int s = 0;
#pragma unroll
        for (int w = 0; w < 8; w++) s += ws[w];
        bsum[blockIdx.x] = s;
    }
}

__global__ __launch_bounds__(256)
void bscan_kernel(const int* __restrict__ bsum, int* __restrict__ boff) {
    int tid = threadIdx.x;
    int v = (tid < NB) ? bsum[tid] : 0;
    int lane = tid & 31, wid = tid >> 5;
    int x = v;
#pragma unroll
    for (int o = 1; o < 32; o <<= 1) {
        int y = __shfl_up_sync(0xffffffffu, x, o);
        if (lane >= o) x += y;
    }
    __shared__ int ws[8];
    if (lane == 31) ws[wid] = x;
    __syncthreads();
    if (wid == 0 && lane < 8) {
        int w = ws[lane];
#pragma unroll
        for (int o = 1; o < 8; o <<= 1) {
            int y = __shfl_up_sync(0x000000ffu, w, o);
            if (lane >= o) w += y;
        }
        ws[lane] = w;
    }
    __syncthreads();
    int incl = x + (wid > 0 ? ws[wid - 1] : 0);
    if (tid < NB) boff[tid] = incl - v;
}

__global__ __launch_bounds__(256)
void scanf_kernel(const int* __restrict__ deg, const int* __restrict__ boff,
                  int* __restrict__ row, int* __restrict__ cursor) {
    int i = blockIdx.x * 256 + threadIdx.x;
    int v = (i < NN) ? deg[i] : 0;
    int lane = threadIdx.x & 31, wid = threadIdx.x >> 5;
    int x = v;
#pragma unroll
    for (int o = 1; o < 32; o <<= 1) {
        int y = __shfl_up_sync(0xffffffffu, x, o);
        if (lane >= o) x += y;
    }
    __shared__ int ws[8];
    if (lane == 31) ws[wid] = x;
    __syncthreads();
    if (wid == 0 && lane < 8) {
        int w = ws[lane];
#pragma unroll
        for (int o = 1; o < 8; o <<= 1) {
            int y = __shfl_up_sync(0x000000ffu, w, o);
            if (lane >= o) w += y;
        }
        ws[lane] = w;
    }
    __syncthreads();
    int excl = x - v + (wid > 0 ? ws[wid - 1] : 0) + boff[blockIdx.x];
    if (i < NN) {
        row[i]    = excl;
        cursor[i] = excl;
    }
}

// ---------------- K5: scatter src indices into CSR order --------------------
__global__ __launch_bounds__(256)
void scatter_kernel(const int* __restrict__ adj, int* __restrict__ cursor,
                    int* __restrict__ srcs) {
    int i = blockIdx.x * blockDim.x + threadIdx.x;
    if (i >= NE) return;
    int s = adj[i];
    int d = adj[NE + i];
    int pos = atomicAdd(&cursor[d], 1);
    srcs[pos] = s;
}

// ---------------- K6: warp-per-node softmax + aggregation (no atomics) ------
// Lane l owns output floats [4l, 4l+4); head = l>>3.  Edge loop unrolled x2
// so the srcs/asrc/hp gathers of two edges are in flight together.
__global__ __launch_bounds__(256)
void agg_kernel(const int* __restrict__ row, const int* __restrict__ deg,
                const int* __restrict__ srcs,
                const float* __restrict__ asrc, const float* __restrict__ adst,
                const float* __restrict__ hp, float* __restrict__ out) {
    int n = (blockIdx.x * blockDim.x + threadIdx.x) >> 5;
    if (n >= NN) return;
    int lane = threadIdx.x & 31;
    int head = lane >> 3;

    int beg = row[n];
    int dn  = deg[n];
    float au = __ldg(&adst[n * NHEADS + head]);

    float accx = 0.f, accy = 0.f, accz = 0.f, accw = 0.f;
    float ssum = 0.f;

    int j = 0;
    for (; j + 2 <= dn; j += 2) {
        int s0 = __ldg(&srcs[beg + j]);
        int s1 = __ldg(&srcs[beg + j + 1]);
        float v0 = __ldg(&asrc[s0 * NHEADS + head]) + au;
        float v1 = __ldg(&asrc[s1 * NHEADS + head]) + au;
        const float4 h0 = *reinterpret_cast<const float4*>(
            hp + (size_t)s0 * OUTF + lane * 4);
        const float4 h1 = *reinterpret_cast<const float4*>(
            hp + (size_t)s1 * OUTF + lane * 4);
        v0 = v0 > 0.f ? v0 : ALPHA_SLOPE * v0;
        v1 = v1 > 0.f ? v1 : ALPHA_SLOPE * v1;
        float e0 = __expf(v0);                 // softmax shift-invariant; |v| small
        float e1 = __expf(v1);
        ssum += e0 + e1;
        accx += e0 * h0.x + e1 * h1.x;
        accy += e0 * h0.y + e1 * h1.y;
        accz += e0 * h0.z + e1 * h1.z;
        accw += e0 * h0.w + e1 * h1.w;
    }
    if (j < dn) {
        int s0 = __ldg(&srcs[beg + j]);
        float v0 = __ldg(&asrc[s0 * NHEADS + head]) + au;
        const float4 h0 = *reinterpret_cast<const float4*>(
            hp + (size_t)s0 * OUTF + lane * 4);
        v0 = v0 > 0.f ? v0 : ALPHA_SLOPE * v0;
        float e0 = __expf(v0);
        ssum += e0;
        accx += e0 * h0.x;
        accy += e0 * h0.y;
        accz += e0 * h0.z;
        accw += e0 * h0.w;
    }
    if (dn > 0) {
        float inv = 1.0f / ssum;
        accx *= inv; accy *= inv; accz *= inv; accw *= inv;
    }
    *reinterpret_cast<float4*>(out + (size_t)n * OUTF + lane * 4) =
        make_float4(accx, accy, accz, accw);
}

// ---------------- launch ----------------------------------------------------
extern "C" void kernel_launch(void* const* d_in, const int* in_sizes, int n_in,
                              void* d_out, int out_size) {
    const float* h   = (const float*)d_in[0];   // [50000, 256]
    const int*   adj = (const int*)  d_in[1];   // [2, 1600000]
    const float* W   = (const float*)d_in[2];   // [256, 128]
    const float* a   = (const float*)d_in[3];   // [64, 4]
    float*       out = (float*)d_out;           // [50000, 128]

    void *p_hp, *p_as, *p_ad, *p_deg, *p_row, *p_cur, *p_srcs, *p_bsum, *p_boff;
    cudaGetSymbolAddress(&p_hp,   g_hprime);
    cudaGetSymbolAddress(&p_as,   g_alpha_src);
    cudaGetSymbolAddress(&p_ad,   g_alpha_dst);
    cudaGetSymbolAddress(&p_deg,  g_deg);
    cudaGetSymbolAddress(&p_row,  g_row);
    cudaGetSymbolAddress(&p_cur,  g_cursor);
    cudaGetSymbolAddress(&p_srcs, g_src_sorted);
    cudaGetSymbolAddress(&p_bsum, g_bsum);
    cudaGetSymbolAddress(&p_boff, g_boff);

    cudaMemsetAsync(p_deg, 0, NN * sizeof(int));

    // 1+2) h_prime = h @ W  (fp32x2) with fused alpha epilogue
    gemm_kernel<<<(NN + BM - 1) / BM, 256>>>(h, W, a, (float*)p_hp,
                                             (float*)p_as, (float*)p_ad);

    // 3) CSR build: histogram -> multi-block scan -> scatter
    hist_kernel<<<(NE + 255) / 256, 256>>>(adj, (int*)p_deg);
    bsum_kernel<<<NB, 256>>>((const int*)p_deg, (int*)p_bsum);
    bscan_kernel<<<1, 256>>>((const int*)p_bsum, (int*)p_boff);
    scanf_kernel<<<NB, 256>>>((const int*)p_deg, (const int*)p_boff,
                              (int*)p_row, (int*)p_cur);
    scatter_kernel<<<(NE + 255) / 256, 256>>>(adj, (int*)p_cur, (int*)p_srcs);

    // 4) warp-per-node gather softmax-aggregate (atomic-free, fused normalize)
    agg_kernel<<<(NN * 32 + 255) / 256, 256>>>(
        (const int*)p_row, (const int*)p_deg, (const int*)p_srcs,
        (const float*)p_as, (const float*)p_ad, (const float*)p_hp, out);
}

// round 10
// speedup vs baseline: 2.1675x; 1.0687x over previous
#include <cuda_runtime.h>
#include <cuda_bf16.h>
#include <cstdint>

// Problem constants (fixed by the dataset).
#define NN      50000
#define NE      1600000
#define IN_DIM  256
#define OUTF    128          // N_HEADS * OUT_DIM
#define NHEADS  4
#define HD      32           // OUT_DIM per head
#define ALPHA_SLOPE 0.2f

#define NB      ((NN + 255) / 256)    // 196 scan blocks
#define GB      ((NN + 127) / 128)    // 391 gemm blocks
#define HB      ((NE + 255) / 256)    // 6250 hist blocks

// ---------------- scratch (device globals; no allocation allowed) -----------
// NOTE: g_deg is zero at module load and re-zeroed by scan_all_kernel each
// launch, so the fused gemm+hist kernel always sees a clean histogram.
__device__ float g_hprime[(size_t)NN * OUTF];     // 25.6 MB
__device__ float g_alpha_src[(size_t)NN * NHEADS];
__device__ float g_alpha_dst[(size_t)NN * NHEADS];
__device__ int   g_deg[NN];
__device__ int   g_row[NN];
__device__ int   g_cursor[NN];
__device__ int   g_src_sorted[NE];                // 6.4 MB

// ---------------- K1: fp32x2 GEMM + fused alpha epilogue + fused hist -------
// Blocks [0, GB): C[NN,128] = A[NN,256] @ B[256,128], plus
//   asrc[n,h] = sum_d C[n,h*32+d] * a[d*4+h]
//   adst[n,h] = sum_d C[n,h*32+d] * a[(32+d)*4+h]
// Blocks [GB, GB+HB): degree histogram of adj[1] (dst) into deg[].
#define BM 128
#define BN 128
#define BK 16
#define TM 8
#define TN 8

#define FMA_F32X2(d, a, b, c) \
    asm("fma.rn.f32x2 %0, %1, %2, %3;" : "=l"(d) : "l"(a), "l"(b), "l"(c))

__global__ __launch_bounds__(256, 2)
void gemm_hist_kernel(const float* __restrict__ A, const float* __restrict__ B,
                      const float* __restrict__ av, float* __restrict__ C,
                      float* __restrict__ asrc, float* __restrict__ adst,
                      const int* __restrict__ adj, int* __restrict__ deg) {
    const int tid = threadIdx.x;           // 256 threads

    if (blockIdx.x >= GB) {
        // ---------------- histogram path ----------------
        int i = (blockIdx.x - GB) * 256 + tid;
        if (i < NE) atomicAdd(&deg[adj[NE + i]], 1);
        return;
    }

    // ---------------- GEMM path ----------------
    __shared__ float As[BK][BM + 4];
    __shared__ float Bs[BK][BN];

    const int m0  = blockIdx.x * BM;
    const int ty  = tid >> 4;              // 0..15
    const int tx  = tid & 15;              // 0..15

    unsigned long long accp[TM][TN / 2];
#pragma unroll
    for (int i = 0; i < TM; i++)
#pragma unroll
        for (int j = 0; j < TN / 2; j++) accp[i][j] = 0ull;

    for (int kt = 0; kt < IN_DIM; kt += BK) {
#pragma unroll
        for (int it = 0; it < 2; it++) {
            int idx = tid + it * 256;      // 0..511
            int row = idx >> 2;            // 0..127
            int c4  = (idx & 3) * 4;       // 0,4,8,12
            float4 v = make_float4(0.f, 0.f, 0.f, 0.f);
            int grow = m0 + row;
            if (grow < NN)
                v = *reinterpret_cast<const float4*>(A + (size_t)grow * IN_DIM + kt + c4);
            As[c4 + 0][row] = v.x;
            As[c4 + 1][row] = v.y;
            As[c4 + 2][row] = v.z;
            As[c4 + 3][row] = v.w;
        }
#pragma unroll
        for (int it = 0; it < 2; it++) {
            int idx = tid + it * 256;
            int row = idx >> 5;            // 0..15
            int col = (idx & 31) * 4;
            *reinterpret_cast<float4*>(&Bs[row][col]) =
                *reinterpret_cast<const float4*>(B + (size_t)(kt + row) * BN + col);
        }
        __syncthreads();

#pragma unroll
        for (int k = 0; k < BK; k++) {
            float4 a0 = *reinterpret_cast<const float4*>(&As[k][ty * TM]);
            float4 a1 = *reinterpret_cast<const float4*>(&As[k][ty * TM + 4]);
            ulonglong2 b01 = *reinterpret_cast<const ulonglong2*>(&Bs[k][tx * TN]);
            ulonglong2 b23 = *reinterpret_cast<const ulonglong2*>(&Bs[k][tx * TN + 4]);
            float ra[TM] = {a0.x, a0.y, a0.z, a0.w, a1.x, a1.y, a1.z, a1.w};
#pragma unroll
            for (int i = 0; i < TM; i++) {
                unsigned long long a2;
                unsigned int rbits = __float_as_uint(ra[i]);
                asm("mov.b64 %0, {%1, %1};" : "=l"(a2) : "r"(rbits));
                FMA_F32X2(accp[i][0], a2, b01.x, accp[i][0]);
                FMA_F32X2(accp[i][1], a2, b01.y, accp[i][1]);
                FMA_F32X2(accp[i][2], a2, b23.x, accp[i][2]);
                FMA_F32X2(accp[i][3], a2, b23.y, accp[i][3]);
            }
        }
        __syncthreads();
    }

    // ---- epilogue: store C tile + fused alpha dot products ------------------
    // This thread's 8 columns (tx*8 .. tx*8+7) all lie in head h = tx>>2.
    const int h      = tx >> 2;
    const int d_base = (tx & 3) * 8;
    float avs[TN], avd[TN];
#pragma unroll
    for (int j = 0; j < TN; j++) {
        avs[j] = __ldg(&av[(d_base + j) * NHEADS + h]);
        avd[j] = __ldg(&av[(32 + d_base + j) * NHEADS + h]);
    }

#pragma unroll
    for (int i = 0; i < TM; i++) {
        int grow = m0 + ty * TM + i;
        const float* f = reinterpret_cast<const float*>(accp[i]);
        if (grow < NN) {
            float4 v0 = make_float4(f[0], f[1], f[2], f[3]);
            float4 v1 = make_float4(f[4], f[5], f[6], f[7]);
            *reinterpret_cast<float4*>(C + (size_t)grow * BN + tx * TN)     = v0;
            *reinterpret_cast<float4*>(C + (size_t)grow * BN + tx * TN + 4) = v1;
        }
        float s = 0.f, t = 0.f;
#pragma unroll
        for (int j = 0; j < TN; j++) {
            s += f[j] * avs[j];
            t += f[j] * avd[j];
        }
        s += __shfl_xor_sync(0xffffffffu, s, 1);
        s += __shfl_xor_sync(0xffffffffu, s, 2);
        t += __shfl_xor_sync(0xffffffffu, t, 1);
        t += __shfl_xor_sync(0xffffffffu, t, 2);
        if (grow < NN && (tx & 3) == 0) {
            asrc[(size_t)grow * NHEADS + h] = s;
            adst[(size_t)grow * NHEADS + h] = t;
        }
    }
}

// ---------------- K2: single-kernel exclusive scan + deg re-zero -------------
// Each block b computes its global offset by summing all degrees of blocks
// 0..b-1 itself (coalesced, L2-resident: total extra reads ~19 MB), then does
// its local 256-element exclusive scan.  Also zeroes deg for the next launch.
__global__ __launch_bounds__(256)
void scan_all_kernel(int* __restrict__ deg, int* __restrict__ row,
                     int* __restrict__ cursor) {
    const int b   = blockIdx.x;
    const int tid = threadIdx.x;
    const int lane = tid & 31, wid = tid >> 5;
    __shared__ int ws[8];
    __shared__ int s_boff;

    // 1) per-thread partial of deg[0 .. b*256)
    int pre = 0;
    for (int k = 0; k < b; k++) pre += deg[k * 256 + tid];   // idx < 49920 < NN
    // block reduce
    int r = pre;
#pragma unroll
    for (int o = 16; o > 0; o >>= 1) r += __shfl_down_sync(0xffffffffu, r, o);
    if (lane == 0) ws[wid] = r;
    __syncthreads();
    if (tid == 0) {
        int s = 0;
#pragma unroll
        for (int w = 0; w < 8; w++) s += ws[w];
        s_boff = s;
    }
    __syncthreads();
    const int boff = s_boff;
    __syncthreads();                       // ws reused below

    // 2) local exclusive scan of this block's 256 degrees
    int i = b * 256 + tid;
    int v = (i < NN) ? deg[i] : 0;
    int x = v;
#pragma unroll
    for (int o = 1; o < 32; o <<= 1) {
        int y = __shfl_up_sync(0xffffffffu, x, o);
        if (lane >= o) x += y;
    }
    if (lane == 31) ws[wid] = x;
    __syncthreads();
    if (wid == 0 && lane < 8) {
        int w = ws[lane];
#pragma unroll
        for (int o = 1; o < 8; o <<= 1) {
            int y = __shfl_up_sync(0x000000ffu, w, o);
            if (lane >= o) w += y;
        }
        ws[lane] = w;
    }
    __syncthreads();
    int excl = x - v + (wid > 0 ? ws[wid - 1] : 0) + boff;
    if (i < NN) {
        row[i]    = excl;
        cursor[i] = excl;
        deg[i]    = 0;                     // clean histogram for next launch
    }
}

// ---------------- K3: scatter src indices into CSR order --------------------
__global__ __launch_bounds__(256)
void scatter_kernel(const int* __restrict__ adj, int* __restrict__ cursor,
                    int* __restrict__ srcs) {
    int i = blockIdx.x * blockDim.x + threadIdx.x;
    if (i >= NE) return;
    int s = adj[i];
    int d = adj[NE + i];
    int pos = atomicAdd(&cursor[d], 1);
    srcs[pos] = s;
}

// ---------------- K4: warp-per-node softmax + aggregation (no atomics) ------
// Lane l owns output floats [4l, 4l+4); head = l>>3.  Edge loop unrolled x2.
// Degree recovered as cursor[n] - row[n] (cursor was advanced by scatter).
__global__ __launch_bounds__(256)
void agg_kernel(const int* __restrict__ row, const int* __restrict__ cur,
                const int* __restrict__ srcs,
                const float* __restrict__ asrc, const float* __restrict__ adst,
                const float* __restrict__ hp, float* __restrict__ out) {
    int n = (blockIdx.x * blockDim.x + threadIdx.x) >> 5;
    if (n >= NN) return;
    int lane = threadIdx.x & 31;
    int head = lane >> 3;

    int beg = row[n];
    int dn  = cur[n] - beg;
    float au = __ldg(&adst[n * NHEADS + head]);

    float accx = 0.f, accy = 0.f, accz = 0.f, accw = 0.f;
    float ssum = 0.f;

    int j = 0;
    for (; j + 2 <= dn; j += 2) {
        int s0 = __ldg(&srcs[beg + j]);
        int s1 = __ldg(&srcs[beg + j + 1]);
        float v0 = __ldg(&asrc[s0 * NHEADS + head]) + au;
        float v1 = __ldg(&asrc[s1 * NHEADS + head]) + au;
        const float4 h0 = *reinterpret_cast<const float4*>(
            hp + (size_t)s0 * OUTF + lane * 4);
        const float4 h1 = *reinterpret_cast<const float4*>(
            hp + (size_t)s1 * OUTF + lane * 4);
        v0 = v0 > 0.f ? v0 : ALPHA_SLOPE * v0;
        v1 = v1 > 0.f ? v1 : ALPHA_SLOPE * v1;
        float e0 = __expf(v0);                 // softmax shift-invariant; |v| small
        float e1 = __expf(v1);
        ssum += e0 + e1;
        accx += e0 * h0.x + e1 * h1.x;
        accy += e0 * h0.y + e1 * h1.y;
        accz += e0 * h0.z + e1 * h1.z;
        accw += e0 * h0.w + e1 * h1.w;
    }
    if (j < dn) {
        int s0 = __ldg(&srcs[beg + j]);
        float v0 = __ldg(&asrc[s0 * NHEADS + head]) + au;
        const float4 h0 = *reinterpret_cast<const float4*>(
            hp + (size_t)s0 * OUTF + lane * 4);
        v0 = v0 > 0.f ? v0 : ALPHA_SLOPE * v0;
        float e0 = __expf(v0);
        ssum += e0;
        accx += e0 * h0.x;
        accy += e0 * h0.y;
        accz += e0 * h0.z;
        accw += e0 * h0.w;
    }
    if (dn > 0) {
        float inv = 1.0f / ssum;
        accx *= inv; accy *= inv; accz *= inv; accw *= inv;
    }
    *reinterpret_cast<float4*>(out + (size_t)n * OUTF + lane * 4) =
        make_float4(accx, accy, accz, accw);
}

// ---------------- launch ----------------------------------------------------
extern "C" void kernel_launch(void* const* d_in, const int* in_sizes, int n_in,
                              void* d_out, int out_size) {
    const float* h   = (const float*)d_in[0];   // [50000, 256]
    const int*   adj = (const int*)  d_in[1];   // [2, 1600000]
    const float* W   = (const float*)d_in[2];   // [256, 128]
    const float* a   = (const float*)d_in[3];   // [64, 4]
    float*       out = (float*)d_out;           // [50000, 128]

    void *p_hp, *p_as, *p_ad, *p_deg, *p_row, *p_cur, *p_srcs;
    cudaGetSymbolAddress(&p_hp,   g_hprime);
    cudaGetSymbolAddress(&p_as,   g_alpha_src);
    cudaGetSymbolAddress(&p_ad,   g_alpha_dst);
    cudaGetSymbolAddress(&p_deg,  g_deg);
    cudaGetSymbolAddress(&p_row,  g_row);
    cudaGetSymbolAddress(&p_cur,  g_cursor);
    cudaGetSymbolAddress(&p_srcs, g_src_sorted);

    // 1) GEMM (+ fused alpha) and histogram in ONE launch (heterogeneous blocks).
    //    deg==0 guaranteed: zero-initialized at load, re-zeroed by scan_all.
    gemm_hist_kernel<<<GB + HB, 256>>>(h, W, a, (float*)p_hp,
                                       (float*)p_as, (float*)p_ad,
                                       adj, (int*)p_deg);

    // 2) single-kernel scan (+ deg re-zero)
    scan_all_kernel<<<NB, 256>>>((int*)p_deg, (int*)p_row, (int*)p_cur);

    // 3) scatter src indices into CSR order
    scatter_kernel<<<(NE + 255) / 256, 256>>>(adj, (int*)p_cur, (int*)p_srcs);

    // 4) warp-per-node gather softmax-aggregate (atomic-free, fused normalize)
    agg_kernel<<<(NN * 32 + 255) / 256, 256>>>(
        (const int*)p_row, (const int*)p_cur, (const int*)p_srcs,
        (const float*)p_as, (const float*)p_ad, (const float*)p_hp, out);
}

// round 12
// speedup vs baseline: 2.3157x; 1.0684x over previous
#include <cuda_runtime.h>
#include <cuda_bf16.h>
#include <cstdint>

// Problem constants (fixed by the dataset).
#define NN      50000
#define NE      1600000
#define IN_DIM  256
#define OUTF    128          // N_HEADS * OUT_DIM
#define NHEADS  4
#define HD      32           // OUT_DIM per head
#define ALPHA_SLOPE 0.2f

#define NB      ((NN + 255) / 256)        // 196 scan blocks
#define GB      ((NN + 127) / 128)        // 391 gemm blocks
#define HB4     ((NE + 1023) / 1024)      // 1563 hist blocks (4 edges/thread)
#define SB4     ((NE + 1023) / 1024)      // 1563 scatter blocks (4 edges/thread)

// Mega-kernel block ranges (dependencies point only to LOWER block indices).
#define HIST_BEG  GB
#define SCAN_BEG  (GB + HB4)
#define SCAT_BEG  (GB + HB4 + NB)
#define MEGA_GRID (GB + HB4 + NB + SB4)

// ---------------- scratch (device globals; no allocation allowed) -----------
// g_deg is zero at module load and re-zeroed by agg_kernel each launch
// (launch-boundary ordered, so the next mega launch always sees a clean
// histogram).  The scan phase is READ-ONLY on deg — no intra-kernel race.
// g_hist_done/g_scan_done are reset by agg_kernel too.
__device__ float g_hprime[(size_t)NN * OUTF];     // 25.6 MB
__device__ float g_alpha_src[(size_t)NN * NHEADS];
__device__ float g_alpha_dst[(size_t)NN * NHEADS];
__device__ int   g_deg[NN];
__device__ int   g_row[NN];
__device__ int   g_cursor[NN];
__device__ int   g_src_sorted[NE];                // 6.4 MB
__device__ int   g_hist_done;
__device__ int   g_scan_done;

// ---------------- sync helpers ----------------------------------------------
__device__ __forceinline__ int ld_acquire(const int* p) {
    int v;
    asm volatile("ld.acquire.gpu.global.b32 %0, [%1];" : "=r"(v) : "l"(p));
    return v;
}
__device__ __forceinline__ void red_release_add(int* p, int v) {
    asm volatile("red.release.gpu.global.add.s32 [%0], %1;" :: "l"(p), "r"(v)
                 : "memory");
}
__device__ __forceinline__ void spin_until(const int* ctr, int target) {
    if (threadIdx.x == 0) {
        while (ld_acquire(ctr) < target) __nanosleep(128);
    }
    __syncthreads();
}

// ---------------- K1 mega: gemm+alpha || hist -> scan -> scatter -------------
#define BM 128
#define BN 128
#define BK 16
#define TM 8
#define TN 8

#define FMA_F32X2(d, a, b, c) \
    asm("fma.rn.f32x2 %0, %1, %2, %3;" : "=l"(d) : "l"(a), "l"(b), "l"(c))

__global__ __launch_bounds__(256, 2)
void mega_kernel(const float* __restrict__ A, const float* __restrict__ B,
                 const float* __restrict__ av, float* __restrict__ C,
                 float* __restrict__ asrc, float* __restrict__ adst,
                 const int* __restrict__ adj, int* __restrict__ deg,
                 int* __restrict__ row, int* __restrict__ cursor,
                 int* __restrict__ srcs) {
    const int tid = threadIdx.x;           // 256 threads
    const int bid = blockIdx.x;

    if (bid >= SCAT_BEG) {
        // ================= scatter phase (waits on scan) =====================
        spin_until(&g_scan_done, NB);
        int base = (bid - SCAT_BEG) * 1024 + tid * 4;
        if (base < NE) {                   // NE % 4 == 0 -> full int4 in-range
            int4 s4 = *reinterpret_cast<const int4*>(adj + base);
            int4 d4 = *reinterpret_cast<const int4*>(adj + NE + base);
            int p0 = atomicAdd(&cursor[d4.x], 1); srcs[p0] = s4.x;
            int p1 = atomicAdd(&cursor[d4.y], 1); srcs[p1] = s4.y;
            int p2 = atomicAdd(&cursor[d4.z], 1); srcs[p2] = s4.z;
            int p3 = atomicAdd(&cursor[d4.w], 1); srcs[p3] = s4.w;
        }
        return;
    }

    if (bid >= SCAN_BEG) {
        // ======= scan phase (waits on hist; READ-ONLY on deg) ================
        spin_until(&g_hist_done, HB4);
        const int b = bid - SCAN_BEG;
        const int lane = tid & 31, wid = tid >> 5;
        __shared__ int ws[8];
        __shared__ int s_boff;

        int pre = 0;
        for (int k = 0; k < b; k++) pre += deg[k * 256 + tid];
        int r = pre;
#pragma unroll
        for (int o = 16; o > 0; o >>= 1) r += __shfl_down_sync(0xffffffffu, r, o);
        if (lane == 0) ws[wid] = r;
        __syncthreads();
        if (tid == 0) {
            int s = 0;
#pragma unroll
            for (int w = 0; w < 8; w++) s += ws[w];
            s_boff = s;
        }
        __syncthreads();
        const int boff = s_boff;
        __syncthreads();                   // ws reused

        int i = b * 256 + tid;
        int v = (i < NN) ? deg[i] : 0;
        int x = v;
#pragma unroll
        for (int o = 1; o < 32; o <<= 1) {
            int y = __shfl_up_sync(0xffffffffu, x, o);
            if (lane >= o) x += y;
        }
        if (lane == 31) ws[wid] = x;
        __syncthreads();
        if (wid == 0 && lane < 8) {
            int w = ws[lane];
#pragma unroll
            for (int o = 1; o < 8; o <<= 1) {
                int y = __shfl_up_sync(0x000000ffu, w, o);
                if (lane >= o) w += y;
            }
            ws[lane] = w;
        }
        __syncthreads();
        int excl = x - v + (wid > 0 ? ws[wid - 1] : 0) + boff;
        if (i < NN) {
            row[i]    = excl;
            cursor[i] = excl;
            // NOTE: deg is NOT zeroed here (would race other scan blocks'
            // prefix reads).  agg_kernel zeroes it after this launch.
        }
        __syncthreads();
        if (tid == 0) red_release_add(&g_scan_done, 1);
        return;
    }

    if (bid >= HIST_BEG) {
        // ================= histogram phase ===================================
        int base = (bid - HIST_BEG) * 1024 + tid * 4;
        if (base < NE) {
            int4 d4 = *reinterpret_cast<const int4*>(adj + NE + base);
            atomicAdd(&deg[d4.x], 1);
            atomicAdd(&deg[d4.y], 1);
            atomicAdd(&deg[d4.z], 1);
            atomicAdd(&deg[d4.w], 1);
        }
        __syncthreads();
        if (tid == 0) red_release_add(&g_hist_done, 1);
        return;
    }

    // ==================== GEMM + fused alpha phase ===========================
    __shared__ float As[BK][BM + 4];
    __shared__ float Bs[BK][BN];

    const int m0 = bid * BM;
    const int ty = tid >> 4;               // 0..15
    const int tx = tid & 15;               // 0..15

    unsigned long long accp[TM][TN / 2];
#pragma unroll
    for (int i = 0; i < TM; i++)
#pragma unroll
        for (int j = 0; j < TN / 2; j++) accp[i][j] = 0ull;

    for (int kt = 0; kt < IN_DIM; kt += BK) {
#pragma unroll
        for (int it = 0; it < 2; it++) {
            int idx = tid + it * 256;      // 0..511
            int rrow = idx >> 2;           // 0..127
            int c4   = (idx & 3) * 4;      // 0,4,8,12
            float4 v = make_float4(0.f, 0.f, 0.f, 0.f);
            int grow = m0 + rrow;
            if (grow < NN)
                v = *reinterpret_cast<const float4*>(A + (size_t)grow * IN_DIM + kt + c4);
            As[c4 + 0][rrow] = v.x;
            As[c4 + 1][rrow] = v.y;
            As[c4 + 2][rrow] = v.z;
            As[c4 + 3][rrow] = v.w;
        }
#pragma unroll
        for (int it = 0; it < 2; it++) {
            int idx = tid + it * 256;
            int rrow = idx >> 5;           // 0..15
            int col  = (idx & 31) * 4;
            *reinterpret_cast<float4*>(&Bs[rrow][col]) =
                *reinterpret_cast<const float4*>(B + (size_t)(kt + rrow) * BN + col);
        }
        __syncthreads();

#pragma unroll
        for (int k = 0; k < BK; k++) {
            float4 a0 = *reinterpret_cast<const float4*>(&As[k][ty * TM]);
            float4 a1 = *reinterpret_cast<const float4*>(&As[k][ty * TM + 4]);
            ulonglong2 b01 = *reinterpret_cast<const ulonglong2*>(&Bs[k][tx * TN]);
            ulonglong2 b23 = *reinterpret_cast<const ulonglong2*>(&Bs[k][tx * TN + 4]);
            float ra[TM] = {a0.x, a0.y, a0.z, a0.w, a1.x, a1.y, a1.z, a1.w};
#pragma unroll
            for (int i = 0; i < TM; i++) {
                unsigned long long a2;
                unsigned int rbits = __float_as_uint(ra[i]);
                asm("mov.b64 %0, {%1, %1};" : "=l"(a2) : "r"(rbits));
                FMA_F32X2(accp[i][0], a2, b01.x, accp[i][0]);
                FMA_F32X2(accp[i][1], a2, b01.y, accp[i][1]);
                FMA_F32X2(accp[i][2], a2, b23.x, accp[i][2]);
                FMA_F32X2(accp[i][3], a2, b23.y, accp[i][3]);
            }
        }
        __syncthreads();
    }

    // epilogue: store C tile + fused alpha dot products
    const int h      = tx >> 2;
    const int d_base = (tx & 3) * 8;
    float avs[TN], avd[TN];
#pragma unroll
    for (int j = 0; j < TN; j++) {
        avs[j] = __ldg(&av[(d_base + j) * NHEADS + h]);
        avd[j] = __ldg(&av[(32 + d_base + j) * NHEADS + h]);
    }

#pragma unroll
    for (int i = 0; i < TM; i++) {
        int grow = m0 + ty * TM + i;
        const float* f = reinterpret_cast<const float*>(accp[i]);
        if (grow < NN) {
            float4 v0 = make_float4(f[0], f[1], f[2], f[3]);
            float4 v1 = make_float4(f[4], f[5], f[6], f[7]);
            *reinterpret_cast<float4*>(C + (size_t)grow * BN + tx * TN)     = v0;
            *reinterpret_cast<float4*>(C + (size_t)grow * BN + tx * TN + 4) = v1;
        }
        float s = 0.f, t = 0.f;
#pragma unroll
        for (int j = 0; j < TN; j++) {
            s += f[j] * avs[j];
            t += f[j] * avd[j];
        }
        s += __shfl_xor_sync(0xffffffffu, s, 1);
        s += __shfl_xor_sync(0xffffffffu, s, 2);
        t += __shfl_xor_sync(0xffffffffu, t, 1);
        t += __shfl_xor_sync(0xffffffffu, t, 2);
        if (grow < NN && (tx & 3) == 0) {
            asrc[(size_t)grow * NHEADS + h] = s;
            adst[(size_t)grow * NHEADS + h] = t;
        }
    }
}

// ---------------- K2: warp-per-node softmax + aggregation (no atomics) ------
// Lane l owns output floats [4l, 4l+4); head = l>>3.  Edge loop unrolled x4.
// Degree recovered as cursor[n] - row[n].  Also zeroes deg[] and resets the
// mega counters for the next launch (launch-boundary ordered => deterministic
// across graph replays).
__global__ __launch_bounds__(256)
void agg_kernel(const int* __restrict__ row, const int* __restrict__ cur,
                const int* __restrict__ srcs,
                const float* __restrict__ asrc, const float* __restrict__ adst,
                const float* __restrict__ hp, float* __restrict__ out,
                int* __restrict__ deg) {
    int gid = blockIdx.x * blockDim.x + threadIdx.x;
    if (gid < NN) deg[gid] = 0;            // clean histogram for next launch
    if (gid == 0) {
        g_hist_done = 0;
        g_scan_done = 0;
    }

    int n = gid >> 5;
    if (n >= NN) return;
    int lane = threadIdx.x & 31;
    int head = lane >> 3;

    int beg = row[n];
    int dn  = cur[n] - beg;
    float au = __ldg(&adst[n * NHEADS + head]);

    float accx = 0.f, accy = 0.f, accz = 0.f, accw = 0.f;
    float ssum = 0.f;

    int j = 0;
    for (; j + 4 <= dn; j += 4) {
        int s0 = __ldg(&srcs[beg + j]);
        int s1 = __ldg(&srcs[beg + j + 1]);
        int s2 = __ldg(&srcs[beg + j + 2]);
        int s3 = __ldg(&srcs[beg + j + 3]);
        float v0 = __ldg(&asrc[s0 * NHEADS + head]) + au;
        float v1 = __ldg(&asrc[s1 * NHEADS + head]) + au;
        float v2 = __ldg(&asrc[s2 * NHEADS + head]) + au;
        float v3 = __ldg(&asrc[s3 * NHEADS + head]) + au;
        const float4 h0 = *reinterpret_cast<const float4*>(hp + (size_t)s0 * OUTF + lane * 4);
        const float4 h1 = *reinterpret_cast<const float4*>(hp + (size_t)s1 * OUTF + lane * 4);
        const float4 h2 = *reinterpret_cast<const float4*>(hp + (size_t)s2 * OUTF + lane * 4);
        const float4 h3 = *reinterpret_cast<const float4*>(hp + (size_t)s3 * OUTF + lane * 4);
        v0 = v0 > 0.f ? v0 : ALPHA_SLOPE * v0;
        v1 = v1 > 0.f ? v1 : ALPHA_SLOPE * v1;
        v2 = v2 > 0.f ? v2 : ALPHA_SLOPE * v2;
        v3 = v3 > 0.f ? v3 : ALPHA_SLOPE * v3;
        float e0 = __expf(v0);             // softmax shift-invariant; |v| small
        float e1 = __expf(v1);
        float e2 = __expf(v2);
        float e3 = __expf(v3);
        ssum += (e0 + e1) + (e2 + e3);
        accx += e0 * h0.x + e1 * h1.x + e2 * h2.x + e3 * h3.x;
        accy += e0 * h0.y + e1 * h1.y + e2 * h2.y + e3 * h3.y;
        accz += e0 * h0.z + e1 * h1.z + e2 * h2.z + e3 * h3.z;
        accw += e0 * h0.w + e1 * h1.w + e2 * h2.w + e3 * h3.w;
    }
    for (; j < dn; ++j) {
        int s0 = __ldg(&srcs[beg + j]);
        float v0 = __ldg(&asrc[s0 * NHEADS + head]) + au;
        const float4 h0 = *reinterpret_cast<const float4*>(hp + (size_t)s0 * OUTF + lane * 4);
        v0 = v0 > 0.f ? v0 : ALPHA_SLOPE * v0;
        float e0 = __expf(v0);
        ssum += e0;
        accx += e0 * h0.x;
        accy += e0 * h0.y;
        accz += e0 * h0.z;
        accw += e0 * h0.w;
    }
    if (dn > 0) {
        float inv = 1.0f / ssum;
        accx *= inv; accy *= inv; accz *= inv; accw *= inv;
    }
    *reinterpret_cast<float4*>(out + (size_t)n * OUTF + lane * 4) =
        make_float4(accx, accy, accz, accw);
}

// ---------------- launch ----------------------------------------------------
extern "C" void kernel_launch(void* const* d_in, const int* in_sizes, int n_in,
                              void* d_out, int out_size) {
    const float* h   = (const float*)d_in[0];   // [50000, 256]
    const int*   adj = (const int*)  d_in[1];   // [2, 1600000]
    const float* W   = (const float*)d_in[2];   // [256, 128]
    const float* a   = (const float*)d_in[3];   // [64, 4]
    float*       out = (float*)d_out;           // [50000, 128]

    void *p_hp, *p_as, *p_ad, *p_deg, *p_row, *p_cur, *p_srcs;
    cudaGetSymbolAddress(&p_hp,   g_hprime);
    cudaGetSymbolAddress(&p_as,   g_alpha_src);
    cudaGetSymbolAddress(&p_ad,   g_alpha_dst);
    cudaGetSymbolAddress(&p_deg,  g_deg);
    cudaGetSymbolAddress(&p_row,  g_row);
    cudaGetSymbolAddress(&p_cur,  g_cursor);
    cudaGetSymbolAddress(&p_srcs, g_src_sorted);

    // 1) one launch: gemm+alpha || hist -> scan -> scatter (device-side sync;
    //    all waits target lower block indices only; scan is read-only on deg).
    mega_kernel<<<MEGA_GRID, 256>>>(h, W, a, (float*)p_hp,
                                    (float*)p_as, (float*)p_ad,
                                    adj, (int*)p_deg,
                                    (int*)p_row, (int*)p_cur, (int*)p_srcs);

    // 2) warp-per-node gather softmax-aggregate (+ deg re-zero, counter reset)
    agg_kernel<<<(NN * 32 + 255) / 256, 256>>>(
        (const int*)p_row, (const int*)p_cur, (const int*)p_srcs,
        (const float*)p_as, (const float*)p_ad, (const float*)p_hp, out,
        (int*)p_deg);
}